// round 9
// baseline (speedup 1.0000x reference)
#include <cuda_runtime.h>
#include <math.h>
#include <float.h>

// ---------------------------------------------------------------------------
// MultiLatentSpaceSimilarity — fp32 f32x2, 8x4 tiles, 3 CTAs/SM,
// cp.async double-buffered tile pipelines; E stored [bhp][s][l],
// V stored [b][s][inner] so all consumer tiles are 16B-copy clean.
// B=16, C=256, S=1024, 3 groups x 8 splits, L=64, HEADS=8, DH=64, INNER=512
// ---------------------------------------------------------------------------

constexpr int B_ = 16, C_ = 256, S_ = 1024;
constexpr int SPLITS_ = 8, L_ = 64, HEADS_ = 8, DH_ = 64, INNER_ = 512;
constexpr float SCALE_ = 0.125f;

// Static device scratch
__device__ float g_K[(size_t)B_ * INNER_ * S_];   // [b][h*64+d][s]
__device__ float g_V[(size_t)B_ * S_ * INNER_];   // [b][s][h*64+d]
__device__ float g_Q[SPLITS_ * L_ * INNER_];      // [p][l][n]
__device__ float g_E[(size_t)B_ * HEADS_ * SPLITS_ * S_ * L_]; // [bhp][s][l]
__device__ float g_Zp[B_ * HEADS_ * SPLITS_ * 8 * L_];         // 8 partial Z
__device__ float g_invZ[B_ * HEADS_ * SPLITS_ * L_];           // 1/Z
__device__ float g_outp[(size_t)4 * 128 * 4 * 64 * 128];       // [sz][bh][rowG][d][row]
__device__ float g_heatp[(size_t)B_ * SPLITS_ * HEADS_ * S_];  // [(b*8+p)*8+h][s]
__device__ float g_distp[B_ * HEADS_ * SPLITS_];

typedef unsigned long long ull;

__device__ __forceinline__ void ffma2(ull& d, ull a, ull b)
{
    asm("fma.rn.f32x2 %0, %1, %2, %0;" : "+l"(d) : "l"(a), "l"(b));
}
__device__ __forceinline__ float2 unpk(ull v)
{
    float2 r;
    asm("mov.b64 {%0, %1}, %2;" : "=f"(r.x), "=f"(r.y) : "l"(v));
    return r;
}
__device__ __forceinline__ ull pack2(float v)
{
    ull r;
    asm("mov.b64 %0, {%1, %1};" : "=l"(r) : "f"(v));
    return r;
}
__device__ __forceinline__ void ld_bcast4(const float* p, ull* w)
{
    float4 b = *(const float4*)p;
    w[0] = pack2(b.x); w[1] = pack2(b.y); w[2] = pack2(b.z); w[3] = pack2(b.w);
}

// cp.async helpers (LDGSTS)
__device__ __forceinline__ void cpa16(float* smem, const float* g)
{
    unsigned a = (unsigned)__cvta_generic_to_shared(smem);
    asm volatile("cp.async.cg.shared.global [%0], [%1], 16;\n"
                 :: "r"(a), "l"(g));
}
__device__ __forceinline__ void cpa_commit()
{
    asm volatile("cp.async.commit_group;\n");
}
__device__ __forceinline__ void cpa_wait1()
{
    asm volatile("cp.async.wait_group 1;\n");
}
__device__ __forceinline__ void cpa_wait0()
{
    asm volatile("cp.async.wait_group 0;\n");
}

// ---------------------------------------------------------------------------
// K/V projection: out = A^T * W. Tile 128(m) x 64(n); tx->4m, wy->8n bcast.
// DST 0: K[b][n][m] (coalesced). DST 1: V[b][m][n] (16B rows per m).
// ---------------------------------------------------------------------------
template <int DST>
__global__ __launch_bounds__(256, 3) void projKV_kernel(
    const float* __restrict__ A, const float* __restrict__ W)
{
    extern __shared__ float sm[];
    float* As = sm;                  // [2][32][128]
    float* Ws = sm + 2 * 32 * 128;   // [2][32][68]

    int tid = threadIdx.x;
    int tx = tid & 31, wy = tid >> 5;
    int m0 = blockIdx.x * 128, n0 = blockIdx.y * 64;
    int batch = blockIdx.z;
    const float* Ab = A + (size_t)batch * C_ * S_;

    auto issue = [&](int t, int buf) {
        float* as = As + buf * 32 * 128;
        float* ws = Ws + buf * 32 * 68;
        int c0 = t * 32;
        #pragma unroll
        for (int it = 0; it < 4; it++) {
            int idx = tid + it * 256;
            int c = idx >> 5, f4 = idx & 31;
            cpa16(&as[c * 128 + f4 * 4],
                  &Ab[(size_t)(c0 + c) * S_ + m0 + f4 * 4]);
        }
        #pragma unroll
        for (int it = 0; it < 2; it++) {
            int idx = tid + it * 256;
            int c = idx >> 4, f4 = idx & 15;
            cpa16(&ws[c * 68 + f4 * 4],
                  &W[(size_t)(c0 + c) * INNER_ + n0 + f4 * 4]);
        }
        cpa_commit();
    };

    ull acc[8][2] = {};                          // [n][m-pair]
    issue(0, 0);
    for (int t = 0; t < 8; t++) {
        if (t < 7) { issue(t + 1, (t + 1) & 1); cpa_wait1(); }
        else       { cpa_wait0(); }
        __syncthreads();
        const float* as = As + (t & 1) * 32 * 128;
        const float* ws = Ws + (t & 1) * 32 * 68;
        #pragma unroll 4
        for (int c = 0; c < 32; c++) {
            ulonglong2 av = *(const ulonglong2*)&as[c * 128 + tx * 4];
            ull wp[4];
            ld_bcast4(&ws[c * 68 + wy * 8], wp);
            #pragma unroll
            for (int ni = 0; ni < 4; ni++) {
                ffma2(acc[ni][0], wp[ni], av.x);
                ffma2(acc[ni][1], wp[ni], av.y);
            }
            ld_bcast4(&ws[c * 68 + wy * 8 + 4], wp);
            #pragma unroll
            for (int ni = 0; ni < 4; ni++) {
                ffma2(acc[4 + ni][0], wp[ni], av.x);
                ffma2(acc[4 + ni][1], wp[ni], av.y);
            }
        }
        if (t < 7) __syncthreads();
    }

    if (DST == 0) {
        #pragma unroll
        for (int ni = 0; ni < 8; ni++) {
            int n = n0 + wy * 8 + ni;
            float2 f0 = unpk(acc[ni][0]), f1 = unpk(acc[ni][1]);
            *(float4*)&g_K[((size_t)batch * INNER_ + n) * S_ + m0 + tx * 4] =
                make_float4(f0.x, f0.y, f1.x, f1.y);
        }
    } else {
        // V[b][m][n]: per m (s), write 8 consecutive n
        #pragma unroll
        for (int j = 0; j < 4; j++) {
            int m = m0 + tx * 4 + j;
            int sj = j >> 1, hi = j & 1;
            float v[8];
            #pragma unroll
            for (int ni = 0; ni < 8; ni++) {
                float2 f = unpk(acc[ni][sj]);
                v[ni] = hi ? f.y : f.x;
            }
            float* vr = &g_V[((size_t)batch * S_ + m) * INNER_ + n0 + wy * 8];
            *(float4*)&vr[0] = make_float4(v[0], v[1], v[2], v[3]);
            *(float4*)&vr[4] = make_float4(v[4], v[5], v[6], v[7]);
        }
    }
}

// ---------------------------------------------------------------------------
// Q projection (small; unchanged). out g_Q[p][l][n]
// ---------------------------------------------------------------------------
__global__ void projQ_kernel(const float* __restrict__ A,
                             const float* __restrict__ W)
{
    __shared__ __align__(16) float As[32][68];   // [c][l]
    __shared__ __align__(16) float Wd[32][132];  // [c][2n] dup
    int tid = threadIdx.x;
    int txq = tid & 15, tyq = tid >> 4;
    int n0 = blockIdx.y * 64;
    int p = blockIdx.z;
    const float* Ab = A + (size_t)p * C_ * L_;

    ull acc[4][2] = {};
    for (int c0 = 0; c0 < C_; c0 += 32) {
        __syncthreads();
        for (int idx = tid; idx < 512; idx += 256) {
            int c = idx >> 4, q = idx & 15;
            *(float4*)&As[c][q * 4] =
                *(const float4*)&Ab[(size_t)(c0 + c) * L_ + q * 4];
            float4 w = *(const float4*)&W[(size_t)(c0 + c) * INNER_ + n0 + q * 4];
            Wd[c][q * 8 + 0] = w.x; Wd[c][q * 8 + 1] = w.x;
            Wd[c][q * 8 + 2] = w.y; Wd[c][q * 8 + 3] = w.y;
            Wd[c][q * 8 + 4] = w.z; Wd[c][q * 8 + 5] = w.z;
            Wd[c][q * 8 + 6] = w.w; Wd[c][q * 8 + 7] = w.w;
        }
        __syncthreads();
        #pragma unroll
        for (int cc = 0; cc < 32; cc++) {
            ulonglong2 am  = *(ulonglong2*)&As[cc][txq * 4];
            ulonglong2 w01 = *(ulonglong2*)&Wd[cc][tyq * 8];
            ulonglong2 w23 = *(ulonglong2*)&Wd[cc][tyq * 8 + 4];
            ffma2(acc[0][0], w01.x, am.x); ffma2(acc[0][1], w01.x, am.y);
            ffma2(acc[1][0], w01.y, am.x); ffma2(acc[1][1], w01.y, am.y);
            ffma2(acc[2][0], w23.x, am.x); ffma2(acc[2][1], w23.x, am.y);
            ffma2(acc[3][0], w23.y, am.x); ffma2(acc[3][1], w23.y, am.y);
        }
    }
    #pragma unroll
    for (int i4 = 0; i4 < 4; i4++) {
        int n = n0 + tyq * 4 + i4;
        float2 a = unpk(acc[i4][0]), b2 = unpk(acc[i4][1]);
        int l = txq * 4;
        g_Q[((size_t)p * L_ + l + 0) * INNER_ + n] = a.x;
        g_Q[((size_t)p * L_ + l + 1) * INNER_ + n] = a.y;
        g_Q[((size_t)p * L_ + l + 2) * INNER_ + n] = b2.x;
        g_Q[((size_t)p * L_ + l + 3) * INNER_ + n] = b2.y;
    }
}

// ---------------------------------------------------------------------------
// Scores: E[bhp][s][l] = exp(SCALE*q.k); Zp partials (8/bhp).
// Grid (8 sq, 1024 bhp). tx->4 s, wy->8 l (bcast). K double-buffered.
// ---------------------------------------------------------------------------
__global__ __launch_bounds__(256, 3) void scores_kernel()
{
    extern __shared__ float sm[];
    float* Kt = sm;                  // [2][32][128]
    float* Qs = sm + 2 * 32 * 128;   // [64][68]  Qs[d][l]

    int sq = blockIdx.x;
    int bhp = blockIdx.y;
    int p = bhp & 7, h = (bhp >> 3) & 7, b = bhp >> 6;
    int s0 = sq * 128;
    int tid = threadIdx.x;
    int tx = tid & 31, wy = tid >> 5;

    const float* kbase = g_K + ((size_t)(b * HEADS_ + h) * DH_) * S_ + s0;
    const float* qbase = g_Q + (size_t)p * L_ * INNER_ + h * DH_;

    auto issue = [&](int t, int buf) {
        float* kt = Kt + buf * 32 * 128;
        int d0 = t * 32;
        #pragma unroll
        for (int it = 0; it < 4; it++) {
            int idx = tid + it * 256;
            int d = idx >> 5, f4 = idx & 31;
            cpa16(&kt[d * 128 + f4 * 4],
                  &kbase[(size_t)(d0 + d) * S_ + f4 * 4]);
        }
        cpa_commit();
    };

    issue(0, 0);
    // Q preload (plain LDG/STS scatter; covered by first barrier)
    #pragma unroll
    for (int it = 0; it < 4; it++) {
        int idx = tid + it * 256;
        int dq = idx & 15, l = idx >> 4;
        float4 q = *(const float4*)&qbase[(size_t)l * INNER_ + dq * 4];
        Qs[(dq * 4 + 0) * 68 + l] = q.x;
        Qs[(dq * 4 + 1) * 68 + l] = q.y;
        Qs[(dq * 4 + 2) * 68 + l] = q.z;
        Qs[(dq * 4 + 3) * 68 + l] = q.w;
    }

    ull acc[8][2] = {};                          // [l][s-pair]
    for (int t = 0; t < 2; t++) {
        if (t == 0) { issue(1, 1); cpa_wait1(); }
        else        { cpa_wait0(); }
        __syncthreads();
        const float* kt = Kt + (t & 1) * 32 * 128;
        #pragma unroll 4
        for (int d = 0; d < 32; d++) {
            ulonglong2 kv = *(const ulonglong2*)&kt[d * 128 + tx * 4];
            ull qp[4];
            ld_bcast4(&Qs[(t * 32 + d) * 68 + wy * 8], qp);
            #pragma unroll
            for (int li = 0; li < 4; li++) {
                ffma2(acc[li][0], qp[li], kv.x);
                ffma2(acc[li][1], qp[li], kv.y);
            }
            ld_bcast4(&Qs[(t * 32 + d) * 68 + wy * 8 + 4], qp);
            #pragma unroll
            for (int li = 0; li < 4; li++) {
                ffma2(acc[4 + li][0], qp[li], kv.x);
                ffma2(acc[4 + li][1], qp[li], kv.y);
            }
        }
    }

    // epilogue: exp, E[bhp][s][l] store (2 float4 per s), partial Z
    float zacc[8] = {};
    float* ebase = g_E + ((size_t)bhp * S_ + s0 + tx * 4) * 64 + wy * 8;
    #pragma unroll
    for (int j = 0; j < 4; j++) {
        int sj = j >> 1, hi = j & 1;
        float e[8];
        #pragma unroll
        for (int li = 0; li < 8; li++) {
            float2 f = unpk(acc[li][sj]);
            float v = hi ? f.y : f.x;
            e[li] = __expf(v * SCALE_);
            zacc[li] += e[li];
        }
        float* ep = ebase + (size_t)j * 64;
        *(float4*)&ep[0] = make_float4(e[0], e[1], e[2], e[3]);
        *(float4*)&ep[4] = make_float4(e[4], e[5], e[6], e[7]);
    }
    #pragma unroll
    for (int li = 0; li < 8; li++) {
        float z = zacc[li];
        #pragma unroll
        for (int off = 16; off; off >>= 1)
            z += __shfl_xor_sync(0xffffffffu, z, off);
        if (tx == 0) g_Zp[(bhp * 8 + sq) * 64 + wy * 8 + li] = z;
    }
}

// ---------------------------------------------------------------------------
// invZ[bhp*64+l] = 1 / sum_j Zp[(bhp*8+j)*64+l]
// ---------------------------------------------------------------------------
__global__ void invz_kernel()
{
    int i = blockIdx.x * 256 + threadIdx.x;
    int bhp = i >> 6, l = i & 63;
    float z = 0.f;
    #pragma unroll
    for (int j = 0; j < 8; j++) z += g_Zp[(bhp * 8 + j) * 64 + l];
    g_invZ[i] = 1.0f / z;
}

// ---------------------------------------------------------------------------
// Out slices: rows = 128 (2 p x 64 l), d = 64, s-slice = 256.
// Grid (4 rowG, 4 sz, 128 bh). Both tiles cp.async, double-buffered.
// ---------------------------------------------------------------------------
__global__ __launch_bounds__(256, 3) void out_slice_kernel()
{
    extern __shared__ float sm[];
    float* Es    = sm;                           // [2][32][132] Es[s][row]
    float* Vs    = sm + 2 * 32 * 132;            // [2][32][68]  Vs[s][d]
    float* invZs = sm + 2 * 32 * 132 + 2 * 32 * 68; // [128]

    int rowG = blockIdx.x;
    int sz   = blockIdx.y;
    int bh   = blockIdx.z;
    int b = bh >> 3, h = bh & 7;
    int tid = threadIdx.x;
    int tx = tid & 31, wy = tid >> 5;

    if (tid < 128)
        invZs[tid] = g_invZ[(bh * 8 + rowG * 2) * 64 + tid];

    const float* vbase = g_V + (size_t)b * S_ * INNER_ + h * DH_;
    size_t ebase0 = (size_t)(bh * 8 + rowG * 2) * S_ * 64;   // E[bhp][s][l]

    auto issue = [&](int c, int buf) {
        int s0 = sz * 256 + c * 32;
        float* es = Es + buf * 32 * 132;
        float* vs = Vs + buf * 32 * 68;
        #pragma unroll
        for (int it = 0; it < 4; it++) {
            int idx = tid + it * 256;
            int f4 = idx & 31, s = idx >> 5;
            int pl = f4 >> 4, l4 = f4 & 15;
            cpa16(&es[s * 132 + pl * 64 + l4 * 4],
                  &g_E[ebase0 + ((size_t)pl * S_ + s0 + s) * 64 + l4 * 4]);
        }
        #pragma unroll
        for (int it = 0; it < 2; it++) {
            int idx = tid + it * 256;
            int f4 = idx & 15, s = idx >> 4;
            cpa16(&vs[s * 68 + f4 * 4],
                  &vbase[(size_t)(s0 + s) * INNER_ + f4 * 4]);
        }
        cpa_commit();
    };

    ull acc[8][2] = {};                          // [d][row-pair]
    issue(0, 0);
    for (int c = 0; c < 8; c++) {
        if (c < 7) { issue(c + 1, (c + 1) & 1); cpa_wait1(); }
        else       { cpa_wait0(); }
        __syncthreads();
        const float* es = Es + (c & 1) * 32 * 132;
        const float* vs = Vs + (c & 1) * 32 * 68;
        #pragma unroll 4
        for (int s = 0; s < 32; s++) {
            ulonglong2 ev = *(const ulonglong2*)&es[s * 132 + tx * 4];
            ull vp[4];
            ld_bcast4(&vs[s * 68 + wy * 8], vp);
            #pragma unroll
            for (int di = 0; di < 4; di++) {
                ffma2(acc[di][0], vp[di], ev.x);
                ffma2(acc[di][1], vp[di], ev.y);
            }
            ld_bcast4(&vs[s * 68 + wy * 8 + 4], vp);
            #pragma unroll
            for (int di = 0; di < 4; di++) {
                ffma2(acc[4 + di][0], vp[di], ev.x);
                ffma2(acc[4 + di][1], vp[di], ev.y);
            }
        }

        // heat: threads 0..63 -> (s_loc 32, p_loc 2)
        if (tid < 64) {
            int s_loc = tid & 31, p_loc = tid >> 5;
            float hacc = 0.f;
            #pragma unroll 16
            for (int l = 0; l < 64; l++)
                hacc += es[s_loc * 132 + p_loc * 64 + l] * invZs[p_loc * 64 + l];
            int p = rowG * 2 + p_loc;
            int s0 = sz * 256 + c * 32;
            g_heatp[((size_t)(b * SPLITS_ + p) * HEADS_ + h) * S_ + s0 + s_loc] = hacc;
        }
        if (c < 7) __syncthreads();
    }

    float* outBase = g_outp +
        (((size_t)(sz * 128 + bh) * 4 + rowG) * 64) * 128;
    #pragma unroll
    for (int di = 0; di < 8; di++) {
        int d = wy * 8 + di;
        float2 f0 = unpk(acc[di][0]), f1 = unpk(acc[di][1]);
        *(float4*)&outBase[(size_t)d * 128 + tx * 4] =
            make_float4(f0.x, f0.y, f1.x, f1.y);
    }
}

// ---------------------------------------------------------------------------
// Finish: per bhp, sum 4 slice partials, normalize, dist = sum (q-out)^2.
// ---------------------------------------------------------------------------
__global__ void finish_kernel()
{
    int bhp = blockIdx.x;
    int p = bhp & 7, h = (bhp >> 3) & 7, b = bhp >> 6;
    int bh = b * 8 + h;
    int rowG = p >> 1, p_loc = p & 1;
    int tid = threadIdx.x;

    const float* qb = g_Q + (size_t)p * L_ * INNER_ + h * DH_;
    float ssum = 0.f;
    #pragma unroll
    for (int it = 0; it < 16; it++) {
        int idx = tid + it * 256;
        int d = idx >> 6, l = idx & 63;
        float v = 0.f;
        #pragma unroll
        for (int sz = 0; sz < 4; sz++)
            v += g_outp[(((size_t)(sz * 128 + bh) * 4 + rowG) * 64 + d) * 128 +
                        p_loc * 64 + l];
        float o = v * g_invZ[bhp * 64 + l];
        float diff = qb[(size_t)l * INNER_ + d] - o;
        ssum += diff * diff;
    }
    __shared__ float red[256];
    red[tid] = ssum;
    __syncthreads();
    for (int off = 128; off > 0; off >>= 1) {
        if (tid < off) red[tid] += red[tid + off];
        __syncthreads();
    }
    if (tid == 0) g_distp[bhp] = red[0];
}

// ---------------------------------------------------------------------------
__global__ void reduce_dist_kernel(float* __restrict__ out, int col0)
{
    int t = threadIdx.x;
    if (t < B_ * SPLITS_) {
        int p = t & 7, b = t >> 3;
        float s = 0.f;
        #pragma unroll
        for (int h = 0; h < HEADS_; h++) s += g_distp[b * 64 + h * 8 + p];
        out[b * 24 + col0 + p] = s * (1.0f / (L_ * INNER_));
    }
}

__global__ void argmax_kernel(float* __restrict__ out, int col0)
{
    int bp = blockIdx.x;
    int p = bp & 7, b = bp >> 3;
    const float* hp = g_heatp + (size_t)bp * HEADS_ * S_;
    int tid = threadIdx.x;

    float best = -FLT_MAX;
    int bidx = 0;
    for (int s = tid; s < S_; s += 256) {
        float v = 0.f;
        #pragma unroll
        for (int h = 0; h < HEADS_; h++) v += hp[(size_t)h * S_ + s];
        if (v > best) { best = v; bidx = s; }
    }
    __shared__ float sv[256];
    __shared__ int si[256];
    sv[tid] = best; si[tid] = bidx;
    __syncthreads();
    for (int off = 128; off > 0; off >>= 1) {
        if (tid < off) {
            bool take = (sv[tid + off] > sv[tid]) ||
                        (sv[tid + off] == sv[tid] && si[tid + off] < si[tid]);
            if (take) { sv[tid] = sv[tid + off]; si[tid] = si[tid + off]; }
        }
        __syncthreads();
    }
    if (tid == 0) out[384 + b * 24 + col0 + p] = (float)si[0];
}

// ---------------------------------------------------------------------------
extern "C" void kernel_launch(void* const* d_in, const int* in_sizes, int n_in,
                              void* d_out, int out_size)
{
    const float* x      = (const float*)d_in[0];
    const float* protos = (const float*)d_in[1];
    const float* Wq     = (const float*)d_in[2];
    const float* Wk     = (const float*)d_in[3];
    const float* Wv     = (const float*)d_in[4];
    float* out = (float*)d_out;

    constexpr int PROJ_SMEM   = (2 * 32 * 128 + 2 * 32 * 68) * 4;          // 50176
    constexpr int SCORES_SMEM = (2 * 32 * 128 + 64 * 68) * 4;              // 50176
    constexpr int OUT_SMEM    = (2 * 32 * 132 + 2 * 32 * 68 + 128) * 4;    // 51712

    cudaFuncSetAttribute(projKV_kernel<0>,
                         cudaFuncAttributeMaxDynamicSharedMemorySize, PROJ_SMEM);
    cudaFuncSetAttribute(projKV_kernel<1>,
                         cudaFuncAttributeMaxDynamicSharedMemorySize, PROJ_SMEM);
    cudaFuncSetAttribute(scores_kernel,
                         cudaFuncAttributeMaxDynamicSharedMemorySize, SCORES_SMEM);
    cudaFuncSetAttribute(out_slice_kernel,
                         cudaFuncAttributeMaxDynamicSharedMemorySize, OUT_SMEM);

    for (int i = 0; i < 3; i++) {
        const float* wq = Wq + (size_t)i * C_ * INNER_;
        const float* wk = Wk + (size_t)i * C_ * INNER_;
        const float* wv = Wv + (size_t)i * C_ * INNER_;

        projKV_kernel<0><<<dim3(S_ / 128, INNER_ / 64, B_), 256, PROJ_SMEM>>>(x, wk);
        projKV_kernel<1><<<dim3(S_ / 128, INNER_ / 64, B_), 256, PROJ_SMEM>>>(x, wv);
        projQ_kernel<<<dim3(1, INNER_ / 64, SPLITS_), 256>>>(
            protos + (size_t)i * SPLITS_ * C_ * L_, wq);

        scores_kernel<<<dim3(8, B_ * HEADS_ * SPLITS_), 256, SCORES_SMEM>>>();
        invz_kernel<<<256, 256>>>();
        out_slice_kernel<<<dim3(4, 4, 128), 256, OUT_SMEM>>>();
        finish_kernel<<<B_ * HEADS_ * SPLITS_, 256>>>();
        reduce_dist_kernel<<<1, 128>>>(out, i * SPLITS_);
        argmax_kernel<<<B_ * SPLITS_, 256>>>(out, i * SPLITS_);
    }
}